// round 2
// baseline (speedup 1.0000x reference)
#include <cuda_runtime.h>
#include <cuda_bf16.h>

#define SS     256   // sequence length
#define BB     64    // batch
#define INF    256   // input features
#define HH     256   // hidden
#define INNER  512
#define AA     64    // action dim
#define LEVELS 7     // DEPTH-1 vertical scans
#define NB     144   // persistent blocks (<= SM count, all co-resident)
#define NT     256   // threads per block

// ------------------- device scratch (static, no allocation) -------------------
__device__ float g_xv[2][SS * BB * HH];      // level input/output (time-major [S,B,H])
__device__ float g_px[SS * BB * INNER];      // precomputed xt@W + b
__device__ float g_pa[SS * BB * AA];         // precomputed xt@W_a1 + b_a1
__device__ float g_xm[2][SS * BB];           // per-level mask  [S,B]
__device__ float g_phv[2][SS * BB];          // per-level phv   [S,B]
__device__ float g_tmp[BB * INNER];          // per-step intermediate
__device__ float g_h[2][BB * HH];            // ping-pong recurrent state
__device__ float g_hv[BB];
__device__ float g_both[BB], g_xonly[BB], g_honly[BB];
// transposed weights (row = output feature, contiguous K)
__device__ float g_WembT[HH * INF];
__device__ float g_WT[INNER * HH];
__device__ float g_UT[INNER * HH];
__device__ float g_W1T[HH * INNER];
__device__ float g_Wa1T[AA * HH];
__device__ float g_Ua1T[AA * HH];

// ------------------- software grid barrier -------------------
__device__ unsigned g_bar_count = 0;
__device__ unsigned g_bar_gen = 0;

__device__ __forceinline__ void gbar() {
    __syncthreads();
    if (threadIdx.x == 0) {
        unsigned gen = *(volatile unsigned*)&g_bar_gen;
        __threadfence();
        if (atomicAdd(&g_bar_count, 1u) == (unsigned)(NB - 1)) {
            g_bar_count = 0;
            __threadfence();
            atomicAdd(&g_bar_gen, 1u);
        } else {
            while (*(volatile unsigned*)&g_bar_gen == gen) { }
        }
        __threadfence();
    }
    __syncthreads();
}

__device__ __forceinline__ float lrelu(float z) { return z >= 0.f ? z : 0.01f * z; }

// ------------------- the persistent kernel -------------------
__global__ void __launch_bounds__(NT)
enc_kernel(const float* __restrict__ x, const float* __restrict__ mask,
           const float* __restrict__ W_emb, const float* __restrict__ b_emb,
           const float* __restrict__ W, const float* __restrict__ U, const float* __restrict__ b,
           const float* __restrict__ W1, const float* __restrict__ b1,
           const float* __restrict__ Wa1, const float* __restrict__ Ua1, const float* __restrict__ ba1,
           const float* __restrict__ Wa3, const float* __restrict__ ba3,
           float* __restrict__ out)
{
    __shared__ float sm[4096 + 512];   // 18 KB: GEMM tiles / h rows / action scratch
    const int tid = threadIdx.x;
    const int bid = blockIdx.x;

    // ---------------- Phase T: weight transposes + mask init ----------------
    for (int idx = bid * NT + tid; idx < HH * INF; idx += NB * NT) {
        int j = idx / INF, k = idx % INF;
        g_WembT[idx] = W_emb[k * HH + j];
    }
    for (int idx = bid * NT + tid; idx < INNER * HH; idx += NB * NT) {
        int c = idx / HH, k = idx % HH;
        g_WT[idx] = W[k * INNER + c];
        g_UT[idx] = U[k * INNER + c];
    }
    for (int idx = bid * NT + tid; idx < HH * INNER; idx += NB * NT) {
        int j = idx / INNER, k = idx % INNER;
        g_W1T[idx] = W1[k * HH + j];
    }
    for (int idx = bid * NT + tid; idx < AA * HH; idx += NB * NT) {
        int j = idx / HH, k = idx % HH;
        g_Wa1T[idx] = Wa1[k * AA + j];
        g_Ua1T[idx] = Ua1[k * AA + j];
    }
    for (int idx = bid * NT + tid; idx < SS * BB; idx += NB * NT) {
        int t = idx / BB, i = idx % BB;
        float m = mask[i * SS + t];
        g_xm[0][idx] = m;
        g_phv[0][idx] = m;
    }
    gbar();

    // ---------------- Phase E: embedding GEMM -> g_xv[0] (time-major) ----------------
    // tiles: 1024 row-groups (16 rows of m=t*B+i) x 4 col-groups (64 cols)
    for (int tile = bid; tile < 1024 * 4; tile += NB) {
        int mt = tile >> 2, cgp = tile & 3;
        int rbase = mt * 16, cbase = cgp * 64;
        for (int u = tid; u < 16 * 64; u += NT) {         // load 16 x-rows (scattered)
            int r = u >> 6, off = (u & 63) << 2;
            int m = rbase + r;
            int i = m & (BB - 1), t = m >> 6;             // m = t*B + i
            *(float4*)&sm[r * INF + off] = *(const float4*)&x[(i * SS + t) * INF + off];
        }
        __syncthreads();
        int c = tid & 63, rq = tid >> 6;
        int jg = cbase + c;
        const float4* wrow = (const float4*)&g_WembT[jg * INF];
        float4 s0 = {0,0,0,0}, s1 = {0,0,0,0}, s2 = {0,0,0,0}, s3 = {0,0,0,0};
        #pragma unroll 8
        for (int k4 = 0; k4 < INF / 4; k4++) {
            float4 wv = wrow[k4];
            float4 x0 = *(const float4*)&sm[(rq     ) * INF + k4 * 4];
            float4 x1 = *(const float4*)&sm[(rq +  4) * INF + k4 * 4];
            float4 x2 = *(const float4*)&sm[(rq +  8) * INF + k4 * 4];
            float4 x3 = *(const float4*)&sm[(rq + 12) * INF + k4 * 4];
            s0.x += x0.x*wv.x; s0.y += x0.y*wv.y; s0.z += x0.z*wv.z; s0.w += x0.w*wv.w;
            s1.x += x1.x*wv.x; s1.y += x1.y*wv.y; s1.z += x1.z*wv.z; s1.w += x1.w*wv.w;
            s2.x += x2.x*wv.x; s2.y += x2.y*wv.y; s2.z += x2.z*wv.z; s2.w += x2.w*wv.w;
            s3.x += x3.x*wv.x; s3.y += x3.y*wv.y; s3.z += x3.z*wv.z; s3.w += x3.w*wv.w;
        }
        float bb = b_emb[jg];
        g_xv[0][(rbase + rq     ) * HH + jg] = (s0.x + s0.y) + (s0.z + s0.w) + bb;
        g_xv[0][(rbase + rq +  4) * HH + jg] = (s1.x + s1.y) + (s1.z + s1.w) + bb;
        g_xv[0][(rbase + rq +  8) * HH + jg] = (s2.x + s2.y) + (s2.z + s2.w) + bb;
        g_xv[0][(rbase + rq + 12) * HH + jg] = (s3.x + s3.y) + (s3.z + s3.w) + bb;
        __syncthreads();
    }
    gbar();

    // ---------------- levels ----------------
    for (int lvl = 0; lvl < LEVELS; lvl++) {
        const int cur = lvl & 1, nxt = cur ^ 1;
        const float* xv = g_xv[cur];

        // ---- Phase P: PX = xv@W + b (8192 tiles), PA = xv@Wa1 + ba1 (1024 tiles) ----
        for (int tile = bid; tile < 9216; tile += NB) {
            int rbase, cbase;
            const float* wT;
            bool is_px = (tile < 8192);
            if (is_px) { int mt = tile >> 3, cg = tile & 7; rbase = mt * 16; cbase = cg * 64; wT = g_WT; }
            else       { int t2 = tile - 8192;              rbase = t2 * 16; cbase = 0;       wT = g_Wa1T; }
            for (int u = tid; u < 16 * 64; u += NT) {       // 16 contiguous xv rows
                int r = u >> 6, off = (u & 63) << 2;
                *(float4*)&sm[r * HH + off] = *(const float4*)&xv[(rbase + r) * HH + off];
            }
            __syncthreads();
            int c = tid & 63, rq = tid >> 6;
            int jg = cbase + c;
            const float4* wrow = (const float4*)&wT[jg * HH];
            float4 s0 = {0,0,0,0}, s1 = {0,0,0,0}, s2 = {0,0,0,0}, s3 = {0,0,0,0};
            #pragma unroll 8
            for (int k4 = 0; k4 < HH / 4; k4++) {
                float4 wv = wrow[k4];
                float4 x0 = *(const float4*)&sm[(rq     ) * HH + k4 * 4];
                float4 x1 = *(const float4*)&sm[(rq +  4) * HH + k4 * 4];
                float4 x2 = *(const float4*)&sm[(rq +  8) * HH + k4 * 4];
                float4 x3 = *(const float4*)&sm[(rq + 12) * HH + k4 * 4];
                s0.x += x0.x*wv.x; s0.y += x0.y*wv.y; s0.z += x0.z*wv.z; s0.w += x0.w*wv.w;
                s1.x += x1.x*wv.x; s1.y += x1.y*wv.y; s1.z += x1.z*wv.z; s1.w += x1.w*wv.w;
                s2.x += x2.x*wv.x; s2.y += x2.y*wv.y; s2.z += x2.z*wv.z; s2.w += x2.w*wv.w;
                s3.x += x3.x*wv.x; s3.y += x3.y*wv.y; s3.z += x3.z*wv.z; s3.w += x3.w*wv.w;
            }
            float r0 = (s0.x + s0.y) + (s0.z + s0.w);
            float r1 = (s1.x + s1.y) + (s1.z + s1.w);
            float r2 = (s2.x + s2.y) + (s2.z + s2.w);
            float r3 = (s3.x + s3.y) + (s3.z + s3.w);
            if (is_px) {
                float bb = b[jg];
                g_px[(rbase + rq     ) * INNER + jg] = r0 + bb;
                g_px[(rbase + rq +  4) * INNER + jg] = r1 + bb;
                g_px[(rbase + rq +  8) * INNER + jg] = r2 + bb;
                g_px[(rbase + rq + 12) * INNER + jg] = r3 + bb;
            } else {
                float bb = ba1[jg];
                g_pa[(rbase + rq     ) * AA + jg] = r0 + bb;
                g_pa[(rbase + rq +  4) * AA + jg] = r1 + bb;
                g_pa[(rbase + rq +  8) * AA + jg] = r2 + bb;
                g_pa[(rbase + rq + 12) * AA + jg] = r3 + bb;
            }
            __syncthreads();
        }
        // per-level state init (owned by last block; no conflict with Phase P targets)
        if (bid == NB - 1) {
            for (int idx = tid; idx < BB * HH; idx += NT) g_h[0][idx] = 0.f;
            if (tid < BB) {
                g_hv[tid] = 0.f;
                g_xm[nxt][(SS - 1) * BB + tid] = 1.f;   // shifted-mask tail = ones
            }
        }
        gbar();

        // ---- Phase S: 256 sequential steps ----
        for (int t = 0; t < SS; t++) {
            const float* hcur = g_h[t & 1];
            float* hnext = g_h[(t + 1) & 1];

            // ======== stage A ========
            if (bid < 128) {
                // tmp[i][c] = lrelu(px + h@U), tile 8 rows x 32 cols, 1 output/thread
                int rg = bid & 7, cg = bid >> 3;
                int rbase = rg * 8, cbase = cg * 32;
                for (int u = tid; u < 8 * 64; u += NT) {
                    int r = u >> 6, off = (u & 63) << 2;
                    *(float4*)&sm[r * HH + off] = *(const float4*)&hcur[(rbase + r) * HH + off];
                }
                __syncthreads();
                int r = tid >> 5, c = tid & 31;
                int i = rbase + r, jg = cbase + c;
                const float4* urow = (const float4*)&g_UT[jg * HH];
                float a0 = 0, a1 = 0, a2 = 0, a3 = 0;
                #pragma unroll 8
                for (int k4 = 0; k4 < HH / 4; k4++) {
                    float4 wv = urow[k4];
                    float4 hv4 = *(const float4*)&sm[r * HH + k4 * 4];
                    a0 += hv4.x * wv.x; a1 += hv4.y * wv.y;
                    a2 += hv4.z * wv.z; a3 += hv4.w * wv.w;
                }
                float acc = (a0 + a1) + (a2 + a3) + g_px[(t * BB + i) * INNER + jg];
                g_tmp[i * INNER + jg] = lrelu(acc);
            } else {
                // action gate: 16 blocks x 4 rows
                int ab = bid - 128;
                int rbase = ab * 4;
                float* hs = sm;
                float* as = sm + 4 * HH;
                for (int u = tid; u < 4 * 64; u += NT) {
                    int r = u >> 6, off = (u & 63) << 2;
                    *(float4*)&hs[r * HH + off] = *(const float4*)&hcur[(rbase + r) * HH + off];
                }
                __syncthreads();
                {
                    int r2 = tid >> 6, j = tid & 63;
                    int i = rbase + r2;
                    const float4* urow = (const float4*)&g_Ua1T[j * HH];
                    float a0 = 0, a1 = 0, a2 = 0, a3 = 0;
                    #pragma unroll 8
                    for (int k4 = 0; k4 < HH / 4; k4++) {
                        float4 wv = urow[k4];
                        float4 hv4 = *(const float4*)&hs[r2 * HH + k4 * 4];
                        a0 += hv4.x * wv.x; a1 += hv4.y * wv.y;
                        a2 += hv4.z * wv.z; a3 += hv4.w * wv.w;
                    }
                    float av = (a0 + a1) + (a2 + a3) + g_pa[(t * BB + i) * AA + j];
                    as[r2 * 64 + j] = lrelu(av);
                }
                __syncthreads();
                int w = tid >> 5, lane = tid & 31;
                if (w < 4) {
                    float p = as[w * 64 + lane] * Wa3[lane] + as[w * 64 + 32 + lane] * Wa3[32 + lane];
                    #pragma unroll
                    for (int o = 16; o; o >>= 1) p += __shfl_xor_sync(0xffffffffu, p, o);
                    if (lane == 0) {
                        int i = rbase + w;
                        float s   = 0.2f * (p + ba3[0]) + 0.5f;
                        float nmr = fminf(fmaxf(s, 0.f), 1.f);
                        float lv  = (t == SS - 1) ? 1.f : 0.f;
                        float pm  = g_xm[cur][t * BB + i];
                        float ph  = g_phv[cur][t * BB + i];
                        float hvp = g_hv[i];
                        float nm   = (1.f - lv) * (pm * ph * nmr);
                        float both = pm * ph * (1.f - nm) * hvp;
                        float xo   = pm * ph * (nm + (1.f - nm) * (1.f - hvp));
                        float ho   = (1.f - pm + pm * (1.f - ph)) * (1.f - nm) * hvp;
                        float hv   = both + xo + ho;
                        g_both[i] = both; g_xonly[i] = xo; g_honly[i] = ho;
                        g_hv[i] = hv;
                        g_phv[nxt][t * BB + i] = hv;
                        if (t > 0) g_xm[nxt][(t - 1) * BB + i] = nm;
                    }
                }
            }
            gbar();

            // ======== stage B ========
            if (bid < 128) {
                // h_[i][j] = lrelu(tmp@W1 + b1); h = both*h_ + xo*xt + ho*h_old
                // tile 8 rows x 16 cols, split-K=2 (two lanes per output)
                int rg = bid & 7, cg = bid >> 3;
                int rbase = rg * 8, cbase = cg * 16;
                for (int u = tid; u < 8 * 128; u += NT) {
                    int r = u >> 7, off = (u & 127) << 2;
                    *(float4*)&sm[r * INNER + off] = *(const float4*)&g_tmp[(rbase + r) * INNER + off];
                }
                __syncthreads();
                int w = tid >> 5, lane = tid & 31;
                int r = w, c = lane >> 1, kh = lane & 1;
                int i = rbase + r, jg = cbase + c;
                const float4* wrow = (const float4*)&g_W1T[jg * INNER + kh * 256];
                const float*  trow = &sm[r * INNER + kh * 256];
                float a0 = 0, a1 = 0, a2 = 0, a3 = 0;
                #pragma unroll 8
                for (int k4 = 0; k4 < 64; k4++) {
                    float4 wv  = wrow[k4];
                    float4 tv4 = *(const float4*)&trow[k4 * 4];
                    a0 += tv4.x * wv.x; a1 += tv4.y * wv.y;
                    a2 += tv4.z * wv.z; a3 += tv4.w * wv.w;
                }
                float acc = (a0 + a1) + (a2 + a3);
                acc += __shfl_xor_sync(0xffffffffu, acc, 1);
                if (kh == 0) {
                    float hval = lrelu(acc + b1[jg]);
                    float xt   = xv[(t * BB + i) * HH + jg];
                    float hold = hcur[i * HH + jg];
                    float hn = g_both[i] * hval + g_xonly[i] * xt + g_honly[i] * hold;
                    hnext[i * HH + jg] = hn;
                    g_xv[nxt][(t * BB + i) * HH + jg] = hn;
                    if (lvl == LEVELS - 1 && t == SS - 1) out[i * HH + jg] = hn;
                }
            }
            gbar();
        }
    }
}

// ------------------- launcher -------------------
extern "C" void kernel_launch(void* const* d_in, const int* in_sizes, int n_in,
                              void* d_out, int out_size) {
    const float* x     = (const float*)d_in[0];
    const float* mask  = (const float*)d_in[1];
    // d_in[2] = bucket_size (== 256, compile-time constant here)
    const float* W_emb = (const float*)d_in[3];
    const float* b_emb = (const float*)d_in[4];
    const float* W     = (const float*)d_in[5];
    const float* U     = (const float*)d_in[6];
    const float* b     = (const float*)d_in[7];
    const float* W1    = (const float*)d_in[8];
    const float* b1    = (const float*)d_in[9];
    const float* Wa1   = (const float*)d_in[10];
    const float* Ua1   = (const float*)d_in[11];
    const float* ba1   = (const float*)d_in[12];
    const float* Wa3   = (const float*)d_in[13];
    const float* ba3   = (const float*)d_in[14];
    float* out = (float*)d_out;

    enc_kernel<<<NB, NT>>>(x, mask, W_emb, b_emb, W, U, b, W1, b1,
                           Wa1, Ua1, ba1, Wa3, ba3, out);
}

// round 4
// speedup vs baseline: 1.9303x; 1.9303x over previous
#include <cuda_runtime.h>
#include <cuda_bf16.h>

#define SS     256
#define BB     64
#define INF    256
#define HH     256
#define INNER  512
#define AA     64
#define LEVELS 7
#define NB     144
#define NT     256

// ------------------- device scratch -------------------
__device__ float g_xv[2][SS * BB * HH];
__device__ float g_px[SS * BB * INNER];
__device__ float g_pa[SS * BB * AA];
__device__ float g_xm[2][SS * BB];
__device__ float g_phv[2][SS * BB];
__device__ float g_tmp[BB * INNER];
__device__ float g_h[2][BB * HH];
__device__ float g_hv[BB];
__device__ float g_both[BB], g_xonly[BB], g_honly[BB];

// ------------------- slot-based grid barrier -------------------
__device__ volatile unsigned g_arrive[NB];
__device__ volatile unsigned g_gen = 0;

__device__ __forceinline__ void gbar(unsigned ep) {
    __syncthreads();
    if (blockIdx.x == 0) {
        int tid = threadIdx.x;
        if (tid >= 1 && tid < NB) {
            while (g_arrive[tid] < ep) { }
        }
        __syncthreads();
        if (tid == 0) { __threadfence(); g_gen = ep; }
        __syncthreads();
    } else {
        if (threadIdx.x == 0) {
            __threadfence();
            g_arrive[blockIdx.x] = ep;
            while (g_gen < ep) { }
            __threadfence();   // acquire before block proceeds
        }
        __syncthreads();
    }
}

__device__ __forceinline__ float lrelu(float z) { return z >= 0.f ? z : 0.01f * z; }

__device__ __forceinline__ void fma4(float4& acc, float s, const float4& v) {
    acc.x = fmaf(s, v.x, acc.x);
    acc.y = fmaf(s, v.y, acc.y);
    acc.z = fmaf(s, v.z, acc.z);
    acc.w = fmaf(s, v.w, acc.w);
}

__device__ __forceinline__ void red4(float4& a, int m) {
    a.x += __shfl_xor_sync(0xffffffffu, a.x, m);
    a.y += __shfl_xor_sync(0xffffffffu, a.y, m);
    a.z += __shfl_xor_sync(0xffffffffu, a.z, m);
    a.w += __shfl_xor_sync(0xffffffffu, a.w, m);
}

// K=256 outer-product dot: 4 output columns (at wp), activations xr[0..255] in smem.
// Weight row stride NSTR; lanes across a warp read consecutive columns -> coalesced.
template<int NSTR>
__device__ __forceinline__ float4 dotrow256(const float* __restrict__ wp,
                                            const float* __restrict__ xr) {
    float4 acc = {0.f, 0.f, 0.f, 0.f};
    #pragma unroll 4
    for (int k = 0; k < 256; k += 4) {
        float4 hx = *(const float4*)&xr[k];
        const float* wk = wp + (size_t)k * NSTR;
        float4 w0 = *(const float4*)&wk[0];
        float4 w1 = *(const float4*)&wk[NSTR];
        float4 w2 = *(const float4*)&wk[2 * NSTR];
        float4 w3 = *(const float4*)&wk[3 * NSTR];
        fma4(acc, hx.x, w0); fma4(acc, hx.y, w1);
        fma4(acc, hx.z, w2); fma4(acc, hx.w, w3);
    }
    return acc;
}

// ------------------- persistent kernel -------------------
__global__ void __launch_bounds__(NT)
enc_kernel(const float* __restrict__ x, const float* __restrict__ mask,
           const float* __restrict__ W_emb, const float* __restrict__ b_emb,
           const float* __restrict__ W, const float* __restrict__ U, const float* __restrict__ b,
           const float* __restrict__ W1, const float* __restrict__ b1,
           const float* __restrict__ Wa1, const float* __restrict__ Ua1, const float* __restrict__ ba1,
           const float* __restrict__ Wa3, const float* __restrict__ ba3,
           float* __restrict__ out)
{
    __shared__ float sm[4160];
    const int tid = threadIdx.x;
    const int bid = blockIdx.x;
    unsigned ep = g_gen;   // persisted epoch base (replay-safe)

    // ---------------- init masks ----------------
    for (int idx = bid * NT + tid; idx < SS * BB; idx += NB * NT) {
        int t = idx / BB, i = idx % BB;
        float m = mask[i * SS + t];
        g_xm[0][idx] = m;
        g_phv[0][idx] = m;
    }
    gbar(++ep);

    // ---------------- Phase E: xe = x @ W_emb + b_emb  (time-major rows m = t*B+i) ----------------
    for (int tile = bid; tile < 4096; tile += NB) {
        int mt = tile >> 2, cg = tile & 3;
        int rbase = mt * 16, cbase = cg * 64;
        for (int u = tid; u < 16 * 64; u += NT) {
            int r = u >> 6, off = (u & 63) * 4;
            int m = rbase + r;
            int i = m & (BB - 1), t = m >> 6;
            *(float4*)&sm[r * INF + off] = *(const float4*)&x[(i * SS + t) * INF + off];
        }
        __syncthreads();
        int r = tid >> 4, q = tid & 15;
        int col = cbase + q * 4;
        float4 acc = dotrow256<HH>(W_emb + col, &sm[r * INF]);
        float4 bv = *(const float4*)&b_emb[col];
        acc.x += bv.x; acc.y += bv.y; acc.z += bv.z; acc.w += bv.w;
        *(float4*)&g_xv[0][(rbase + r) * HH + col] = acc;
        __syncthreads();
    }
    gbar(++ep);

    // ---------------- levels ----------------
    for (int lvl = 0; lvl < LEVELS; lvl++) {
        const int cur = lvl & 1, nxt = cur ^ 1;
        const float* xv = g_xv[cur];

        // ---- Phase P: PX = xv@W + b  (8192 tiles) ; PA = xv@Wa1 + ba1 (1024 tiles) ----
        for (int tile = bid; tile < 9216; tile += NB) {
            bool is_px = (tile < 8192);
            int rbase, cbase;
            if (is_px) { rbase = (tile >> 3) * 16; cbase = (tile & 7) * 64; }
            else       { rbase = (tile - 8192) * 16; cbase = 0; }
            for (int u = tid; u < 16 * 64; u += NT) {
                int r = u >> 6, off = (u & 63) * 4;
                *(float4*)&sm[r * HH + off] = *(const float4*)&xv[(rbase + r) * HH + off];
            }
            __syncthreads();
            int r = tid >> 4, q = tid & 15;
            if (is_px) {
                int col = cbase + q * 4;
                float4 acc = dotrow256<INNER>(W + col, &sm[r * HH]);
                float4 bv = *(const float4*)&b[col];
                acc.x += bv.x; acc.y += bv.y; acc.z += bv.z; acc.w += bv.w;
                *(float4*)&g_px[(rbase + r) * INNER + col] = acc;
            } else {
                int col = q * 4;
                float4 acc = dotrow256<AA>(Wa1 + col, &sm[r * HH]);
                float4 bv = *(const float4*)&ba1[col];
                acc.x += bv.x; acc.y += bv.y; acc.z += bv.z; acc.w += bv.w;
                *(float4*)&g_pa[(rbase + r) * AA + col] = acc;
            }
            __syncthreads();
        }
        // per-level state init
        if (bid == NB - 1) {
            for (int idx = tid; idx < BB * HH; idx += NT) g_h[0][idx] = 0.f;
            if (tid < BB) {
                g_hv[tid] = 0.f;
                g_xm[nxt][(SS - 1) * BB + tid] = 1.f;
            }
        }
        gbar(++ep);

        // ---- Phase S: 256 sequential steps ----
        for (int t = 0; t < SS; t++) {
            const float* hcur = g_h[t & 1];
            float* hnext = g_h[(t + 1) & 1];

            // ======== stage A ========
            if (bid < 128) {
                // tmp[64,512]: block = (sg: 8 samples) x (cg: 32 cols). 4-way K-split in warp.
                int rbase = (bid & 7) * 8, cbase = (bid >> 3) * 32;
                for (int u = tid; u < 8 * 64; u += NT) {
                    int r = u >> 6, off = (u & 63) * 4;
                    *(float4*)&sm[r * HH + off] = *(const float4*)&hcur[(rbase + r) * HH + off];
                }
                __syncthreads();
                int r = tid >> 5, lane = tid & 31;
                int ks = lane >> 3, q = lane & 7;          // ks in [0,4), q in [0,8)
                const float* up = U + cbase + q * 4;       // row stride INNER
                const float* hr = &sm[r * HH + ks * 64];
                float4 acc = {0.f, 0.f, 0.f, 0.f};
                #pragma unroll 4
                for (int kk = 0; kk < 64; kk += 4) {
                    float4 hx = *(const float4*)&hr[kk];
                    const float* uk = up + (size_t)(ks * 64 + kk) * INNER;
                    float4 w0 = *(const float4*)&uk[0];
                    float4 w1 = *(const float4*)&uk[INNER];
                    float4 w2 = *(const float4*)&uk[2 * INNER];
                    float4 w3 = *(const float4*)&uk[3 * INNER];
                    fma4(acc, hx.x, w0); fma4(acc, hx.y, w1);
                    fma4(acc, hx.z, w2); fma4(acc, hx.w, w3);
                }
                red4(acc, 8); red4(acc, 16);
                if (ks == 0) {
                    int i = rbase + r, col = cbase + q * 4;
                    float4 pxv = *(const float4*)&g_px[(t * BB + i) * INNER + col];
                    float4 o;
                    o.x = lrelu(acc.x + pxv.x); o.y = lrelu(acc.y + pxv.y);
                    o.z = lrelu(acc.z + pxv.z); o.w = lrelu(acc.w + pxv.w);
                    *(float4*)&g_tmp[i * INNER + col] = o;
                }
            } else {
                // ---- action gate: 16 blocks x 4 samples ----
                int rbase = (bid - 128) * 4;
                float* as = sm + 2048;                      // partials area
                for (int u = tid; u < 4 * 64; u += NT) {
                    int r = u >> 6, off = (u & 63) * 4;
                    *(float4*)&sm[r * HH + off] = *(const float4*)&hcur[(rbase + r) * HH + off];
                }
                __syncthreads();
                {
                    int w = tid >> 5, lane = tid & 31;
                    int r = w >> 1, kh = w & 1;             // 4 samples x 2 K-halves
                    int ks = lane >> 4, j4 = lane & 15;     // 2-way K-split x 16 col-quads
                    const float* up = Ua1 + j4 * 4;         // row stride AA
                    const float* hr = &sm[r * HH + kh * 128 + ks * 64];
                    float4 acc = {0.f, 0.f, 0.f, 0.f};
                    #pragma unroll 4
                    for (int kk = 0; kk < 64; kk += 4) {
                        float4 hx = *(const float4*)&hr[kk];
                        const float* uk = up + (size_t)(kh * 128 + ks * 64 + kk) * AA;
                        float4 w0 = *(const float4*)&uk[0];
                        float4 w1 = *(const float4*)&uk[AA];
                        float4 w2 = *(const float4*)&uk[2 * AA];
                        float4 w3 = *(const float4*)&uk[3 * AA];
                        fma4(acc, hx.x, w0); fma4(acc, hx.y, w1);
                        fma4(acc, hx.z, w2); fma4(acc, hx.w, w3);
                    }
                    red4(acc, 16);
                    if (ks == 0)
                        *(float4*)&as[((r * 2 + kh) * 16 + j4) * 4] = acc;
                }
                __syncthreads();
                {
                    int w = tid >> 5, lane = tid & 31;
                    if (w < 4) {
                        int i = rbase + w;
                        float p = 0.f;
                        if (lane < 16) {
                            float4 p0 = *(const float4*)&as[((w * 2 + 0) * 16 + lane) * 4];
                            float4 p1 = *(const float4*)&as[((w * 2 + 1) * 16 + lane) * 4];
                            float4 pav = *(const float4*)&g_pa[(t * BB + i) * AA + lane * 4];
                            float a0 = lrelu(p0.x + p1.x + pav.x);
                            float a1 = lrelu(p0.y + p1.y + pav.y);
                            float a2 = lrelu(p0.z + p1.z + pav.z);
                            float a3 = lrelu(p0.w + p1.w + pav.w);
                            float4 w3v = *(const float4*)&Wa3[lane * 4];
                            p = a0 * w3v.x + a1 * w3v.y + a2 * w3v.z + a3 * w3v.w;
                        }
                        #pragma unroll
                        for (int o = 16; o; o >>= 1) p += __shfl_xor_sync(0xffffffffu, p, o);
                        if (lane == 0) {
                            float s   = 0.2f * (p + ba3[0]) + 0.5f;
                            float nmr = fminf(fmaxf(s, 0.f), 1.f);
                            float lv  = (t == SS - 1) ? 1.f : 0.f;
                            float pm  = g_xm[cur][t * BB + i];
                            float ph  = g_phv[cur][t * BB + i];
                            float hvp = g_hv[i];
                            float nm   = (1.f - lv) * (pm * ph * nmr);
                            float both = pm * ph * (1.f - nm) * hvp;
                            float xo   = pm * ph * (nm + (1.f - nm) * (1.f - hvp));
                            float ho   = (1.f - pm + pm * (1.f - ph)) * (1.f - nm) * hvp;
                            float hv   = both + xo + ho;
                            g_both[i] = both; g_xonly[i] = xo; g_honly[i] = ho;
                            g_hv[i] = hv;
                            g_phv[nxt][t * BB + i] = hv;
                            if (t > 0) g_xm[nxt][(t - 1) * BB + i] = nm;
                        }
                    }
                }
            }
            gbar(++ep);

            // ======== stage B ========
            if (bid < 128) {
                // h[64,256]: block = (sg: 8 samples) x (cg: 16 cols). 8-way K-split in warp.
                int rbase = (bid & 7) * 8, cbase = (bid >> 3) * 16;
                for (int u = tid; u < 8 * 128; u += NT) {
                    int r = u >> 7, off = (u & 127) * 4;
                    *(float4*)&sm[r * INNER + off] = *(const float4*)&g_tmp[(rbase + r) * INNER + off];
                }
                __syncthreads();
                int r = tid >> 5, lane = tid & 31;
                int ks = lane >> 2, q = lane & 3;           // ks in [0,8), q in [0,4)
                const float* wp = W1 + cbase + q * 4;       // row stride HH
                const float* tr = &sm[r * INNER];
                float4 acc = {0.f, 0.f, 0.f, 0.f};
                #pragma unroll 4
                for (int kk = 0; kk < 512; kk += 32) {
                    int k = kk + ks * 4;
                    float4 tx = *(const float4*)&tr[k];
                    const float* wk = wp + (size_t)k * HH;
                    float4 w0 = *(const float4*)&wk[0];
                    float4 w1 = *(const float4*)&wk[HH];
                    float4 w2 = *(const float4*)&wk[2 * HH];
                    float4 w3 = *(const float4*)&wk[3 * HH];
                    fma4(acc, tx.x, w0); fma4(acc, tx.y, w1);
                    fma4(acc, tx.z, w2); fma4(acc, tx.w, w3);
                }
                red4(acc, 4); red4(acc, 8); red4(acc, 16);
                if (ks == 0) {
                    int i = rbase + r, col = cbase + q * 4;
                    float4 b1v = *(const float4*)&b1[col];
                    float h0 = lrelu(acc.x + b1v.x);
                    float h1 = lrelu(acc.y + b1v.y);
                    float h2 = lrelu(acc.z + b1v.z);
                    float h3 = lrelu(acc.w + b1v.w);
                    float bo = g_both[i], xo = g_xonly[i], ho = g_honly[i];
                    float4 xt4  = *(const float4*)&xv[(t * BB + i) * HH + col];
                    float4 hol4 = *(const float4*)&hcur[i * HH + col];
                    float4 hn;
                    hn.x = bo * h0 + xo * xt4.x + ho * hol4.x;
                    hn.y = bo * h1 + xo * xt4.y + ho * hol4.y;
                    hn.z = bo * h2 + xo * xt4.z + ho * hol4.z;
                    hn.w = bo * h3 + xo * xt4.w + ho * hol4.w;
                    *(float4*)&hnext[i * HH + col] = hn;
                    *(float4*)&g_xv[nxt][(t * BB + i) * HH + col] = hn;
                    if (lvl == LEVELS - 1 && t == SS - 1)
                        *(float4*)&out[i * HH + col] = hn;
                }
            }
            gbar(++ep);
        }
    }
}

// ------------------- launcher -------------------
extern "C" void kernel_launch(void* const* d_in, const int* in_sizes, int n_in,
                              void* d_out, int out_size) {
    const float* x     = (const float*)d_in[0];
    const float* mask  = (const float*)d_in[1];
    const float* W_emb = (const float*)d_in[3];
    const float* b_emb = (const float*)d_in[4];
    const float* W     = (const float*)d_in[5];
    const float* U     = (const float*)d_in[6];
    const float* b     = (const float*)d_in[7];
    const float* W1    = (const float*)d_in[8];
    const float* b1    = (const float*)d_in[9];
    const float* Wa1   = (const float*)d_in[10];
    const float* Ua1   = (const float*)d_in[11];
    const float* ba1   = (const float*)d_in[12];
    const float* Wa3   = (const float*)d_in[13];
    const float* ba3   = (const float*)d_in[14];
    float* out = (float*)d_out;

    enc_kernel<<<NB, NT>>>(x, mask, W_emb, b_emb, W, U, b, W1, b1,
                           Wa1, Ua1, ba1, Wa3, ba3, out);
}

// round 5
// speedup vs baseline: 2.0017x; 1.0369x over previous
#include <cuda_runtime.h>
#include <cuda_bf16.h>

#define SS     256
#define BB     64
#define INF    256
#define HH     256
#define INNER  512
#define AA     64
#define LEVELS 7
#define NB     144
#define NT     256

// ------------------- device scratch -------------------
__device__ float g_xv[2][SS * BB * HH];
__device__ float g_px[SS * BB * INNER];
__device__ float g_pa[SS * BB * AA];
__device__ float g_xm[2][SS * BB];
__device__ float g_phv[2][SS * BB];
__device__ float g_tmp[BB * INNER];
__device__ float g_h[2][BB * HH];
__device__ float g_hv[BB];
__device__ float g_both[BB], g_xonly[BB], g_honly[BB];

// ------------------- slot-based grid barrier -------------------
__device__ volatile unsigned g_arrive[NB];
__device__ volatile unsigned g_gen = 0;

__device__ __forceinline__ void gbar(unsigned ep) {
    __syncthreads();
    if (blockIdx.x == 0) {
        int tid = threadIdx.x;
        if (tid >= 1 && tid < NB) {
            while (g_arrive[tid] < ep) { }
        }
        __syncthreads();
        if (tid == 0) { __threadfence(); g_gen = ep; }
        __syncthreads();
    } else {
        if (threadIdx.x == 0) {
            __threadfence();
            g_arrive[blockIdx.x] = ep;
            while (g_gen < ep) { }
            __threadfence();   // acquire before block proceeds
        }
        __syncthreads();
    }
}

__device__ __forceinline__ float lrelu(float z) { return z >= 0.f ? z : 0.01f * z; }

__device__ __forceinline__ void fma4(float4& acc, float s, const float4& v) {
    acc.x = fmaf(s, v.x, acc.x);
    acc.y = fmaf(s, v.y, acc.y);
    acc.z = fmaf(s, v.z, acc.z);
    acc.w = fmaf(s, v.w, acc.w);
}

__device__ __forceinline__ void red4(float4& a, int m) {
    a.x += __shfl_xor_sync(0xffffffffu, a.x, m);
    a.y += __shfl_xor_sync(0xffffffffu, a.y, m);
    a.z += __shfl_xor_sync(0xffffffffu, a.z, m);
    a.w += __shfl_xor_sync(0xffffffffu, a.w, m);
}

// K=256 outer-product dot: 4 output columns (at wp), activations xr[0..255] in smem.
// Weight row stride NSTR; lanes across a warp read consecutive columns -> coalesced.
template<int NSTR>
__device__ __forceinline__ float4 dotrow256(const float* __restrict__ wp,
                                            const float* __restrict__ xr) {
    float4 acc = {0.f, 0.f, 0.f, 0.f};
    #pragma unroll 4
    for (int k = 0; k < 256; k += 4) {
        float4 hx = *(const float4*)&xr[k];
        const float* wk = wp + (size_t)k * NSTR;
        float4 w0 = *(const float4*)&wk[0];
        float4 w1 = *(const float4*)&wk[NSTR];
        float4 w2 = *(const float4*)&wk[2 * NSTR];
        float4 w3 = *(const float4*)&wk[3 * NSTR];
        fma4(acc, hx.x, w0); fma4(acc, hx.y, w1);
        fma4(acc, hx.z, w2); fma4(acc, hx.w, w3);
    }
    return acc;
}

// ------------------- persistent kernel -------------------
__global__ void __launch_bounds__(NT)
enc_kernel(const float* __restrict__ x, const float* __restrict__ mask,
           const float* __restrict__ W_emb, const float* __restrict__ b_emb,
           const float* __restrict__ W, const float* __restrict__ U, const float* __restrict__ b,
           const float* __restrict__ W1, const float* __restrict__ b1,
           const float* __restrict__ Wa1, const float* __restrict__ Ua1, const float* __restrict__ ba1,
           const float* __restrict__ Wa3, const float* __restrict__ ba3,
           float* __restrict__ out)
{
    __shared__ float sm[4160];
    const int tid = threadIdx.x;
    const int bid = blockIdx.x;
    unsigned ep = g_gen;   // persisted epoch base (replay-safe)

    // ---------------- init masks ----------------
    for (int idx = bid * NT + tid; idx < SS * BB; idx += NB * NT) {
        int t = idx / BB, i = idx % BB;
        float m = mask[i * SS + t];
        g_xm[0][idx] = m;
        g_phv[0][idx] = m;
    }
    gbar(++ep);

    // ---------------- Phase E: xe = x @ W_emb + b_emb  (time-major rows m = t*B+i) ----------------
    for (int tile = bid; tile < 4096; tile += NB) {
        int mt = tile >> 2, cg = tile & 3;
        int rbase = mt * 16, cbase = cg * 64;
        for (int u = tid; u < 16 * 64; u += NT) {
            int r = u >> 6, off = (u & 63) * 4;
            int m = rbase + r;
            int i = m & (BB - 1), t = m >> 6;
            *(float4*)&sm[r * INF + off] = *(const float4*)&x[(i * SS + t) * INF + off];
        }
        __syncthreads();
        int r = tid >> 4, q = tid & 15;
        int col = cbase + q * 4;
        float4 acc = dotrow256<HH>(W_emb + col, &sm[r * INF]);
        float4 bv = *(const float4*)&b_emb[col];
        acc.x += bv.x; acc.y += bv.y; acc.z += bv.z; acc.w += bv.w;
        *(float4*)&g_xv[0][(rbase + r) * HH + col] = acc;
        __syncthreads();
    }
    gbar(++ep);

    // ---------------- levels ----------------
    for (int lvl = 0; lvl < LEVELS; lvl++) {
        const int cur = lvl & 1, nxt = cur ^ 1;
        const float* xv = g_xv[cur];

        // ---- Phase P: PX = xv@W + b  (8192 tiles) ; PA = xv@Wa1 + ba1 (1024 tiles) ----
        for (int tile = bid; tile < 9216; tile += NB) {
            bool is_px = (tile < 8192);
            int rbase, cbase;
            if (is_px) { rbase = (tile >> 3) * 16; cbase = (tile & 7) * 64; }
            else       { rbase = (tile - 8192) * 16; cbase = 0; }
            for (int u = tid; u < 16 * 64; u += NT) {
                int r = u >> 6, off = (u & 63) * 4;
                *(float4*)&sm[r * HH + off] = *(const float4*)&xv[(rbase + r) * HH + off];
            }
            __syncthreads();
            int r = tid >> 4, q = tid & 15;
            if (is_px) {
                int col = cbase + q * 4;
                float4 acc = dotrow256<INNER>(W + col, &sm[r * HH]);
                float4 bv = *(const float4*)&b[col];
                acc.x += bv.x; acc.y += bv.y; acc.z += bv.z; acc.w += bv.w;
                *(float4*)&g_px[(rbase + r) * INNER + col] = acc;
            } else {
                int col = q * 4;
                float4 acc = dotrow256<AA>(Wa1 + col, &sm[r * HH]);
                float4 bv = *(const float4*)&ba1[col];
                acc.x += bv.x; acc.y += bv.y; acc.z += bv.z; acc.w += bv.w;
                *(float4*)&g_pa[(rbase + r) * AA + col] = acc;
            }
            __syncthreads();
        }
        // per-level state init
        if (bid == NB - 1) {
            for (int idx = tid; idx < BB * HH; idx += NT) g_h[0][idx] = 0.f;
            if (tid < BB) {
                g_hv[tid] = 0.f;
                g_xm[nxt][(SS - 1) * BB + tid] = 1.f;
            }
        }
        gbar(++ep);

        // ---- Phase S: 256 sequential steps ----
        for (int t = 0; t < SS; t++) {
            const float* hcur = g_h[t & 1];
            float* hnext = g_h[(t + 1) & 1];

            // ======== stage A ========
            if (bid < 128) {
                // tmp[64,512]: block = (sg: 8 samples) x (cg: 32 cols). 4-way K-split in warp.
                int rbase = (bid & 7) * 8, cbase = (bid >> 3) * 32;
                for (int u = tid; u < 8 * 64; u += NT) {
                    int r = u >> 6, off = (u & 63) * 4;
                    *(float4*)&sm[r * HH + off] = *(const float4*)&hcur[(rbase + r) * HH + off];
                }
                __syncthreads();
                int r = tid >> 5, lane = tid & 31;
                int ks = lane >> 3, q = lane & 7;          // ks in [0,4), q in [0,8)
                const float* up = U + cbase + q * 4;       // row stride INNER
                const float* hr = &sm[r * HH + ks * 64];
                float4 acc = {0.f, 0.f, 0.f, 0.f};
                #pragma unroll 4
                for (int kk = 0; kk < 64; kk += 4) {
                    float4 hx = *(const float4*)&hr[kk];
                    const float* uk = up + (size_t)(ks * 64 + kk) * INNER;
                    float4 w0 = *(const float4*)&uk[0];
                    float4 w1 = *(const float4*)&uk[INNER];
                    float4 w2 = *(const float4*)&uk[2 * INNER];
                    float4 w3 = *(const float4*)&uk[3 * INNER];
                    fma4(acc, hx.x, w0); fma4(acc, hx.y, w1);
                    fma4(acc, hx.z, w2); fma4(acc, hx.w, w3);
                }
                red4(acc, 8); red4(acc, 16);
                if (ks == 0) {
                    int i = rbase + r, col = cbase + q * 4;
                    float4 pxv = *(const float4*)&g_px[(t * BB + i) * INNER + col];
                    float4 o;
                    o.x = lrelu(acc.x + pxv.x); o.y = lrelu(acc.y + pxv.y);
                    o.z = lrelu(acc.z + pxv.z); o.w = lrelu(acc.w + pxv.w);
                    *(float4*)&g_tmp[i * INNER + col] = o;
                }
            } else {
                // ---- action gate: 16 blocks x 4 samples ----
                int rbase = (bid - 128) * 4;
                float* as = sm + 2048;                      // partials area
                for (int u = tid; u < 4 * 64; u += NT) {
                    int r = u >> 6, off = (u & 63) * 4;
                    *(float4*)&sm[r * HH + off] = *(const float4*)&hcur[(rbase + r) * HH + off];
                }
                __syncthreads();
                {
                    int w = tid >> 5, lane = tid & 31;
                    int r = w >> 1, kh = w & 1;             // 4 samples x 2 K-halves
                    int ks = lane >> 4, j4 = lane & 15;     // 2-way K-split x 16 col-quads
                    const float* up = Ua1 + j4 * 4;         // row stride AA
                    const float* hr = &sm[r * HH + kh * 128 + ks * 64];
                    float4 acc = {0.f, 0.f, 0.f, 0.f};
                    #pragma unroll 4
                    for (int kk = 0; kk < 64; kk += 4) {
                        float4 hx = *(const float4*)&hr[kk];
                        const float* uk = up + (size_t)(kh * 128 + ks * 64 + kk) * AA;
                        float4 w0 = *(const float4*)&uk[0];
                        float4 w1 = *(const float4*)&uk[AA];
                        float4 w2 = *(const float4*)&uk[2 * AA];
                        float4 w3 = *(const float4*)&uk[3 * AA];
                        fma4(acc, hx.x, w0); fma4(acc, hx.y, w1);
                        fma4(acc, hx.z, w2); fma4(acc, hx.w, w3);
                    }
                    red4(acc, 16);
                    if (ks == 0)
                        *(float4*)&as[((r * 2 + kh) * 16 + j4) * 4] = acc;
                }
                __syncthreads();
                {
                    int w = tid >> 5, lane = tid & 31;
                    if (w < 4) {
                        int i = rbase + w;
                        float p = 0.f;
                        if (lane < 16) {
                            float4 p0 = *(const float4*)&as[((w * 2 + 0) * 16 + lane) * 4];
                            float4 p1 = *(const float4*)&as[((w * 2 + 1) * 16 + lane) * 4];
                            float4 pav = *(const float4*)&g_pa[(t * BB + i) * AA + lane * 4];
                            float a0 = lrelu(p0.x + p1.x + pav.x);
                            float a1 = lrelu(p0.y + p1.y + pav.y);
                            float a2 = lrelu(p0.z + p1.z + pav.z);
                            float a3 = lrelu(p0.w + p1.w + pav.w);
                            float4 w3v = *(const float4*)&Wa3[lane * 4];
                            p = a0 * w3v.x + a1 * w3v.y + a2 * w3v.z + a3 * w3v.w;
                        }
                        #pragma unroll
                        for (int o = 16; o; o >>= 1) p += __shfl_xor_sync(0xffffffffu, p, o);
                        if (lane == 0) {
                            float s   = 0.2f * (p + ba3[0]) + 0.5f;
                            float nmr = fminf(fmaxf(s, 0.f), 1.f);
                            float lv  = (t == SS - 1) ? 1.f : 0.f;
                            float pm  = g_xm[cur][t * BB + i];
                            float ph  = g_phv[cur][t * BB + i];
                            float hvp = g_hv[i];
                            float nm   = (1.f - lv) * (pm * ph * nmr);
                            float both = pm * ph * (1.f - nm) * hvp;
                            float xo   = pm * ph * (nm + (1.f - nm) * (1.f - hvp));
                            float ho   = (1.f - pm + pm * (1.f - ph)) * (1.f - nm) * hvp;
                            float hv   = both + xo + ho;
                            g_both[i] = both; g_xonly[i] = xo; g_honly[i] = ho;
                            g_hv[i] = hv;
                            g_phv[nxt][t * BB + i] = hv;
                            if (t > 0) g_xm[nxt][(t - 1) * BB + i] = nm;
                        }
                    }
                }
            }
            gbar(++ep);

            // ======== stage B ========
            if (bid < 128) {
                // h[64,256]: block = (sg: 8 samples) x (cg: 16 cols). 8-way K-split in warp.
                int rbase = (bid & 7) * 8, cbase = (bid >> 3) * 16;
                for (int u = tid; u < 8 * 128; u += NT) {
                    int r = u >> 7, off = (u & 127) * 4;
                    *(float4*)&sm[r * INNER + off] = *(const float4*)&g_tmp[(rbase + r) * INNER + off];
                }
                __syncthreads();
                int r = tid >> 5, lane = tid & 31;
                int ks = lane >> 2, q = lane & 3;           // ks in [0,8), q in [0,4)
                const float* wp = W1 + cbase + q * 4;       // row stride HH
                const float* tr = &sm[r * INNER];
                float4 acc = {0.f, 0.f, 0.f, 0.f};
                #pragma unroll 4
                for (int kk = 0; kk < 512; kk += 32) {
                    int k = kk + ks * 4;
                    float4 tx = *(const float4*)&tr[k];
                    const float* wk = wp + (size_t)k * HH;
                    float4 w0 = *(const float4*)&wk[0];
                    float4 w1 = *(const float4*)&wk[HH];
                    float4 w2 = *(const float4*)&wk[2 * HH];
                    float4 w3 = *(const float4*)&wk[3 * HH];
                    fma4(acc, tx.x, w0); fma4(acc, tx.y, w1);
                    fma4(acc, tx.z, w2); fma4(acc, tx.w, w3);
                }
                red4(acc, 4); red4(acc, 8); red4(acc, 16);
                if (ks == 0) {
                    int i = rbase + r, col = cbase + q * 4;
                    float4 b1v = *(const float4*)&b1[col];
                    float h0 = lrelu(acc.x + b1v.x);
                    float h1 = lrelu(acc.y + b1v.y);
                    float h2 = lrelu(acc.z + b1v.z);
                    float h3 = lrelu(acc.w + b1v.w);
                    float bo = g_both[i], xo = g_xonly[i], ho = g_honly[i];
                    float4 xt4  = *(const float4*)&xv[(t * BB + i) * HH + col];
                    float4 hol4 = *(const float4*)&hcur[i * HH + col];
                    float4 hn;
                    hn.x = bo * h0 + xo * xt4.x + ho * hol4.x;
                    hn.y = bo * h1 + xo * xt4.y + ho * hol4.y;
                    hn.z = bo * h2 + xo * xt4.z + ho * hol4.z;
                    hn.w = bo * h3 + xo * xt4.w + ho * hol4.w;
                    *(float4*)&hnext[i * HH + col] = hn;
                    *(float4*)&g_xv[nxt][(t * BB + i) * HH + col] = hn;
                    if (lvl == LEVELS - 1 && t == SS - 1)
                        *(float4*)&out[i * HH + col] = hn;
                }
            }
            gbar(++ep);
        }
    }
}

// ------------------- launcher -------------------
extern "C" void kernel_launch(void* const* d_in, const int* in_sizes, int n_in,
                              void* d_out, int out_size) {
    const float* x     = (const float*)d_in[0];
    const float* mask  = (const float*)d_in[1];
    const float* W_emb = (const float*)d_in[3];
    const float* b_emb = (const float*)d_in[4];
    const float* W     = (const float*)d_in[5];
    const float* U     = (const float*)d_in[6];
    const float* b     = (const float*)d_in[7];
    const float* W1    = (const float*)d_in[8];
    const float* b1    = (const float*)d_in[9];
    const float* Wa1   = (const float*)d_in[10];
    const float* Ua1   = (const float*)d_in[11];
    const float* ba1   = (const float*)d_in[12];
    const float* Wa3   = (const float*)d_in[13];
    const float* ba3   = (const float*)d_in[14];
    float* out = (float*)d_out;

    enc_kernel<<<NB, NT>>>(x, mask, W_emb, b_emb, W, U, b, W1, b1,
                           Wa1, Ua1, ba1, Wa3, ba3, out);
}